// round 1
// baseline (speedup 1.0000x reference)
#include <cuda_runtime.h>
#include <math.h>

#define NN 8192
#define HH 512
#define TAU 0.8f
#define LAM 0.5f
#define EPSV 1e-8f

// ---------------- device scratch (no allocations allowed) ----------------
__device__ float g_zp_mp[NN * HH];
__device__ float g_zp_sc[NN * HH];
__device__ float g_h[NN * HH];
__device__ float g_inv_mp[NN];
__device__ float g_inv_sc[NN];
__device__ float g_rowsum[NN];
__device__ float g_colsum[NN];
__device__ float g_pmp[NN];
__device__ float g_psc[NN];

// ---------------- zero accumulators ----------------
__global__ void zero_kernel() {
    int i = blockIdx.x * blockDim.x + threadIdx.x;
    if (i < NN) {
        g_rowsum[i] = 0.f;
        g_colsum[i] = 0.f;
        g_pmp[i] = 0.f;
        g_psc[i] = 0.f;
    }
}

// ---------------- MLP GEMM: C[M x 512] = act(A[M x 512] @ W[512 x 512]^T + b) ----------------
// block tile 128x128, K-chunk 16, 256 threads (16x16), 8x8 per thread
template <bool ELU>
__global__ void mlp_gemm_kernel(const float* __restrict__ A,
                                const float* __restrict__ W,
                                const float* __restrict__ bias,
                                float* __restrict__ C) {
    __shared__ float As[16][128];
    __shared__ float Bs[16][128];
    const int ib = blockIdx.y * 128;
    const int jb = blockIdx.x * 128;
    const int tid = threadIdx.x;
    const int tx = tid & 15, ty = tid >> 4;

    float acc[8][8] = {};

    for (int k0 = 0; k0 < HH; k0 += 16) {
#pragma unroll
        for (int l = 0; l < 2; l++) {
            int idx = tid * 2 + l;           // 0..511
            int row = idx >> 2;              // 0..127
            int kv = (idx & 3) * 4;          // 0,4,8,12
            float4 a = *(const float4*)(A + (size_t)(ib + row) * HH + k0 + kv);
            As[kv + 0][row] = a.x; As[kv + 1][row] = a.y;
            As[kv + 2][row] = a.z; As[kv + 3][row] = a.w;
            float4 w = *(const float4*)(W + (size_t)(jb + row) * HH + k0 + kv);
            Bs[kv + 0][row] = w.x; Bs[kv + 1][row] = w.y;
            Bs[kv + 2][row] = w.z; Bs[kv + 3][row] = w.w;
        }
        __syncthreads();
#pragma unroll
        for (int kk = 0; kk < 16; kk++) {
            float4 a0 = *(const float4*)&As[kk][ty * 8];
            float4 a1 = *(const float4*)&As[kk][ty * 8 + 4];
            float4 b0 = *(const float4*)&Bs[kk][tx * 8];
            float4 b1 = *(const float4*)&Bs[kk][tx * 8 + 4];
            float av[8] = {a0.x, a0.y, a0.z, a0.w, a1.x, a1.y, a1.z, a1.w};
            float bv[8] = {b0.x, b0.y, b0.z, b0.w, b1.x, b1.y, b1.z, b1.w};
#pragma unroll
            for (int m = 0; m < 8; m++)
#pragma unroll
                for (int n = 0; n < 8; n++)
                    acc[m][n] = fmaf(av[m], bv[n], acc[m][n]);
        }
        __syncthreads();
    }

#pragma unroll
    for (int m = 0; m < 8; m++) {
        int i = ib + ty * 8 + m;
#pragma unroll
        for (int n = 0; n < 8; n++) {
            int j = jb + tx * 8 + n;
            float x = acc[m][n] + bias[j];
            if (ELU) x = (x > 0.f) ? x : (expf(x) - 1.f);
            C[(size_t)i * HH + j] = x;
        }
    }
}

// ---------------- row inverse norms ----------------
__global__ void norm_kernel(const float* __restrict__ Z, float* __restrict__ inv) {
    int row = blockIdx.x;
    int t = threadIdx.x;  // 128 threads, HH/4 = 128 float4s
    const float4* zr = (const float4*)(Z + (size_t)row * HH);
    float4 v = zr[t];
    float s = v.x * v.x + v.y * v.y + v.z * v.z + v.w * v.w;
#pragma unroll
    for (int o = 16; o > 0; o >>= 1) s += __shfl_down_sync(0xffffffffu, s, o);
    __shared__ float sred[4];
    if ((t & 31) == 0) sred[t >> 5] = s;
    __syncthreads();
    if (t == 0) inv[row] = rsqrtf(sred[0] + sred[1] + sred[2] + sred[3]);
}

// ---------------- fused pairwise kernel ----------------
// E[i][j] = exp( (zp_mp_i . zp_sc_j) * inv_i * inv_j / TAU ), tile 128x128
// accumulates rowsum, colsum, Pmp (pos[i][j]-weighted), Psc (pos[j][i]-weighted)
__global__ void pair_kernel(const int* __restrict__ pos) {
    __shared__ float As[16][128];
    __shared__ float Bs[16][128];
    __shared__ float red[256 * 8];  // 8 KB reduction buffer

    const int ib = blockIdx.y * 128;
    const int jb = blockIdx.x * 128;
    const int tid = threadIdx.x;
    const int tx = tid & 15, ty = tid >> 4;

    float acc[8][8] = {};

    for (int k0 = 0; k0 < HH; k0 += 16) {
#pragma unroll
        for (int l = 0; l < 2; l++) {
            int idx = tid * 2 + l;
            int row = idx >> 2;
            int kv = (idx & 3) * 4;
            float4 a = *(const float4*)(g_zp_mp + (size_t)(ib + row) * HH + k0 + kv);
            As[kv + 0][row] = a.x; As[kv + 1][row] = a.y;
            As[kv + 2][row] = a.z; As[kv + 3][row] = a.w;
            float4 b = *(const float4*)(g_zp_sc + (size_t)(jb + row) * HH + k0 + kv);
            Bs[kv + 0][row] = b.x; Bs[kv + 1][row] = b.y;
            Bs[kv + 2][row] = b.z; Bs[kv + 3][row] = b.w;
        }
        __syncthreads();
#pragma unroll
        for (int kk = 0; kk < 16; kk++) {
            float4 a0 = *(const float4*)&As[kk][ty * 8];
            float4 a1 = *(const float4*)&As[kk][ty * 8 + 4];
            float4 b0 = *(const float4*)&Bs[kk][tx * 8];
            float4 b1 = *(const float4*)&Bs[kk][tx * 8 + 4];
            float av[8] = {a0.x, a0.y, a0.z, a0.w, a1.x, a1.y, a1.z, a1.w};
            float bv[8] = {b0.x, b0.y, b0.z, b0.w, b1.x, b1.y, b1.z, b1.w};
#pragma unroll
            for (int m = 0; m < 8; m++)
#pragma unroll
                for (int n = 0; n < 8; n++)
                    acc[m][n] = fmaf(av[m], bv[n], acc[m][n]);
        }
        __syncthreads();
    }

    // epilogue: exponentiate in registers, accumulate statistics
    float inm[8], inj[8];
#pragma unroll
    for (int m = 0; m < 8; m++) inm[m] = g_inv_mp[ib + ty * 8 + m] * (1.0f / TAU);
#pragma unroll
    for (int n = 0; n < 8; n++) inj[n] = g_inv_sc[jb + tx * 8 + n];

    float rs[8] = {}, cs[8] = {}, pm[8] = {}, ps[8] = {};
#pragma unroll
    for (int m = 0; m < 8; m++)
#pragma unroll
        for (int n = 0; n < 8; n++) {
            float e = expf(acc[m][n] * inm[m] * inj[n]);
            acc[m][n] = e;
            rs[m] += e;
            cs[n] += e;
        }

    // Pmp: pos[i][j] (coalesced int4 row reads)
#pragma unroll
    for (int m = 0; m < 8; m++) {
        size_t base = (size_t)(ib + ty * 8 + m) * NN + jb + tx * 8;
        int4 p0 = *(const int4*)(pos + base);
        int4 p1 = *(const int4*)(pos + base + 4);
        float pv[8] = {(float)p0.x, (float)p0.y, (float)p0.z, (float)p0.w,
                       (float)p1.x, (float)p1.y, (float)p1.z, (float)p1.w};
#pragma unroll
        for (int n = 0; n < 8; n++) pm[m] = fmaf(acc[m][n], pv[n], pm[m]);
    }

    // Psc: pos[j][i] (int4 reads along i; L1 reuses lines within the tile)
#pragma unroll
    for (int n = 0; n < 8; n++) {
        size_t base = (size_t)(jb + tx * 8 + n) * NN + ib + ty * 8;
        int4 p0 = *(const int4*)(pos + base);
        int4 p1 = *(const int4*)(pos + base + 4);
        float pv[8] = {(float)p0.x, (float)p0.y, (float)p0.z, (float)p0.w,
                       (float)p1.x, (float)p1.y, (float)p1.z, (float)p1.w};
#pragma unroll
        for (int m = 0; m < 8; m++) ps[n] = fmaf(acc[m][n], pv[m], ps[n]);
    }

    // block reductions (one global atomic per row/col element per block)
    // rowsum
    __syncthreads();
#pragma unroll
    for (int m = 0; m < 8; m++) red[tid * 8 + m] = rs[m];
    __syncthreads();
    if (tid < 128) {
        int r = tid, tyb = r >> 3, mm = r & 7;
        float s = 0.f;
#pragma unroll
        for (int t2 = 0; t2 < 16; t2++) s += red[(tyb * 16 + t2) * 8 + mm];
        atomicAdd(&g_rowsum[ib + r], s);
    }
    __syncthreads();
    // Pmp
#pragma unroll
    for (int m = 0; m < 8; m++) red[tid * 8 + m] = pm[m];
    __syncthreads();
    if (tid < 128) {
        int r = tid, tyb = r >> 3, mm = r & 7;
        float s = 0.f;
#pragma unroll
        for (int t2 = 0; t2 < 16; t2++) s += red[(tyb * 16 + t2) * 8 + mm];
        atomicAdd(&g_pmp[ib + r], s);
    }
    __syncthreads();
    // colsum
#pragma unroll
    for (int n = 0; n < 8; n++) red[tid * 8 + n] = cs[n];
    __syncthreads();
    if (tid < 128) {
        int c = tid, txb = c >> 3, nn2 = c & 7;
        float s = 0.f;
#pragma unroll
        for (int t2 = 0; t2 < 16; t2++) s += red[(t2 * 16 + txb) * 8 + nn2];
        atomicAdd(&g_colsum[jb + c], s);
    }
    __syncthreads();
    // Psc
#pragma unroll
    for (int n = 0; n < 8; n++) red[tid * 8 + n] = ps[n];
    __syncthreads();
    if (tid < 128) {
        int c = tid, txb = c >> 3, nn2 = c & 7;
        float s = 0.f;
#pragma unroll
        for (int t2 = 0; t2 < 16; t2++) s += red[(t2 * 16 + txb) * 8 + nn2];
        atomicAdd(&g_psc[jb + c], s);
    }
}

// ---------------- final scalar reduction ----------------
__global__ void final_kernel(float* __restrict__ out) {
    int t = threadIdx.x;  // 256
    float s = 0.f;
    for (int i = t; i < NN; i += 256) {
        float lmp = logf(g_pmp[i]) - logf(g_rowsum[i] + EPSV);
        float lsc = logf(g_psc[i]) - logf(g_colsum[i] + EPSV);
        s += LAM * lmp + (1.0f - LAM) * lsc;
    }
#pragma unroll
    for (int o = 16; o > 0; o >>= 1) s += __shfl_down_sync(0xffffffffu, s, o);
    __shared__ float sr[8];
    if ((t & 31) == 0) sr[t >> 5] = s;
    __syncthreads();
    if (t == 0) {
        float tot = 0.f;
#pragma unroll
        for (int w = 0; w < 8; w++) tot += sr[w];
        out[0] = -tot / (float)NN;
    }
}

// ---------------- launch ----------------
extern "C" void kernel_launch(void* const* d_in, const int* in_sizes, int n_in,
                              void* d_out, int out_size) {
    const float* z_mp = (const float*)d_in[0];
    const float* z_sc = (const float*)d_in[1];
    const int* pos = (const int*)d_in[2];
    const float* W1 = (const float*)d_in[3];
    const float* b1 = (const float*)d_in[4];
    const float* W2 = (const float*)d_in[5];
    const float* b2 = (const float*)d_in[6];

    float *p_h, *p_zp_mp, *p_zp_sc, *p_inv_mp, *p_inv_sc;
    cudaGetSymbolAddress((void**)&p_h, g_h);
    cudaGetSymbolAddress((void**)&p_zp_mp, g_zp_mp);
    cudaGetSymbolAddress((void**)&p_zp_sc, g_zp_sc);
    cudaGetSymbolAddress((void**)&p_inv_mp, g_inv_mp);
    cudaGetSymbolAddress((void**)&p_inv_sc, g_inv_sc);

    zero_kernel<<<NN / 256, 256>>>();

    dim3 mlp_grid(HH / 128, NN / 128);
    mlp_gemm_kernel<true><<<mlp_grid, 256>>>(z_mp, W1, b1, p_h);
    mlp_gemm_kernel<false><<<mlp_grid, 256>>>(p_h, W2, b2, p_zp_mp);
    mlp_gemm_kernel<true><<<mlp_grid, 256>>>(z_sc, W1, b1, p_h);
    mlp_gemm_kernel<false><<<mlp_grid, 256>>>(p_h, W2, b2, p_zp_sc);

    norm_kernel<<<NN, 128>>>(p_zp_mp, p_inv_mp);
    norm_kernel<<<NN, 128>>>(p_zp_sc, p_inv_sc);

    pair_kernel<<<dim3(NN / 128, NN / 128), 256>>>(pos);

    final_kernel<<<1, 256>>>((float*)d_out);
}

// round 2
// speedup vs baseline: 1.0023x; 1.0023x over previous
#include <cuda_runtime.h>
#include <math.h>

#define NN 8192
#define HH 512
#define TAU 0.8f
#define LAM 0.5f
#define EPSV 1e-8f

// ---------------- device scratch (no allocations allowed) ----------------
__device__ float g_zp_mp[NN * HH];
__device__ float g_zp_sc[NN * HH];
__device__ float g_h[NN * HH];
__device__ float g_inv_mp[NN];
__device__ float g_inv_sc[NN];
__device__ float g_rowsum[NN];
__device__ float g_colsum[NN];
__device__ float g_pmp[NN];
__device__ float g_psc[NN];

// ---------------- zero accumulators ----------------
__global__ void zero_kernel() {
    int i = blockIdx.x * blockDim.x + threadIdx.x;
    if (i < NN) {
        g_rowsum[i] = 0.f;
        g_colsum[i] = 0.f;
        g_pmp[i] = 0.f;
        g_psc[i] = 0.f;
    }
}

// ---------------- MLP GEMM: C[M x 512] = act(A[M x 512] @ W[512 x 512]^T + b) ----------------
// block tile 128x128, K-chunk 16, 256 threads (16x16), 8x8 per thread
template <bool ELU>
__global__ void mlp_gemm_kernel(const float* __restrict__ A,
                                const float* __restrict__ W,
                                const float* __restrict__ bias,
                                float* __restrict__ C) {
    __shared__ float As[16][128];
    __shared__ float Bs[16][128];
    const int ib = blockIdx.y * 128;
    const int jb = blockIdx.x * 128;
    const int tid = threadIdx.x;
    const int tx = tid & 15, ty = tid >> 4;

    float acc[8][8] = {};

    for (int k0 = 0; k0 < HH; k0 += 16) {
#pragma unroll
        for (int l = 0; l < 2; l++) {
            int idx = tid * 2 + l;           // 0..511
            int row = idx >> 2;              // 0..127
            int kv = (idx & 3) * 4;          // 0,4,8,12
            float4 a = *(const float4*)(A + (size_t)(ib + row) * HH + k0 + kv);
            As[kv + 0][row] = a.x; As[kv + 1][row] = a.y;
            As[kv + 2][row] = a.z; As[kv + 3][row] = a.w;
            float4 w = *(const float4*)(W + (size_t)(jb + row) * HH + k0 + kv);
            Bs[kv + 0][row] = w.x; Bs[kv + 1][row] = w.y;
            Bs[kv + 2][row] = w.z; Bs[kv + 3][row] = w.w;
        }
        __syncthreads();
#pragma unroll
        for (int kk = 0; kk < 16; kk++) {
            float4 a0 = *(const float4*)&As[kk][ty * 8];
            float4 a1 = *(const float4*)&As[kk][ty * 8 + 4];
            float4 b0 = *(const float4*)&Bs[kk][tx * 8];
            float4 b1 = *(const float4*)&Bs[kk][tx * 8 + 4];
            float av[8] = {a0.x, a0.y, a0.z, a0.w, a1.x, a1.y, a1.z, a1.w};
            float bv[8] = {b0.x, b0.y, b0.z, b0.w, b1.x, b1.y, b1.z, b1.w};
#pragma unroll
            for (int m = 0; m < 8; m++)
#pragma unroll
                for (int n = 0; n < 8; n++)
                    acc[m][n] = fmaf(av[m], bv[n], acc[m][n]);
        }
        __syncthreads();
    }

#pragma unroll
    for (int m = 0; m < 8; m++) {
        int i = ib + ty * 8 + m;
#pragma unroll
        for (int n = 0; n < 8; n++) {
            int j = jb + tx * 8 + n;
            float x = acc[m][n] + bias[j];
            if (ELU) x = (x > 0.f) ? x : (expf(x) - 1.f);
            C[(size_t)i * HH + j] = x;
        }
    }
}

// ---------------- row inverse norms ----------------
__global__ void norm_kernel(const float* __restrict__ Z, float* __restrict__ inv) {
    int row = blockIdx.x;
    int t = threadIdx.x;  // 128 threads, HH/4 = 128 float4s
    const float4* zr = (const float4*)(Z + (size_t)row * HH);
    float4 v = zr[t];
    float s = v.x * v.x + v.y * v.y + v.z * v.z + v.w * v.w;
#pragma unroll
    for (int o = 16; o > 0; o >>= 1) s += __shfl_down_sync(0xffffffffu, s, o);
    __shared__ float sred[4];
    if ((t & 31) == 0) sred[t >> 5] = s;
    __syncthreads();
    if (t == 0) inv[row] = rsqrtf(sred[0] + sred[1] + sred[2] + sred[3]);
}

// ---------------- fused pairwise kernel ----------------
// E[i][j] = exp( (zp_mp_i . zp_sc_j) * inv_i * inv_j / TAU ), tile 128x128
// accumulates rowsum, colsum, Pmp (pos[i][j]-weighted), Psc (pos[j][i]-weighted)
__global__ void pair_kernel(const int* __restrict__ pos) {
    __shared__ float As[16][128];
    __shared__ float Bs[16][128];
    __shared__ float red[256 * 8];  // 8 KB reduction buffer

    const int ib = blockIdx.y * 128;
    const int jb = blockIdx.x * 128;
    const int tid = threadIdx.x;
    const int tx = tid & 15, ty = tid >> 4;

    float acc[8][8] = {};

    for (int k0 = 0; k0 < HH; k0 += 16) {
#pragma unroll
        for (int l = 0; l < 2; l++) {
            int idx = tid * 2 + l;
            int row = idx >> 2;
            int kv = (idx & 3) * 4;
            float4 a = *(const float4*)(g_zp_mp + (size_t)(ib + row) * HH + k0 + kv);
            As[kv + 0][row] = a.x; As[kv + 1][row] = a.y;
            As[kv + 2][row] = a.z; As[kv + 3][row] = a.w;
            float4 b = *(const float4*)(g_zp_sc + (size_t)(jb + row) * HH + k0 + kv);
            Bs[kv + 0][row] = b.x; Bs[kv + 1][row] = b.y;
            Bs[kv + 2][row] = b.z; Bs[kv + 3][row] = b.w;
        }
        __syncthreads();
#pragma unroll
        for (int kk = 0; kk < 16; kk++) {
            float4 a0 = *(const float4*)&As[kk][ty * 8];
            float4 a1 = *(const float4*)&As[kk][ty * 8 + 4];
            float4 b0 = *(const float4*)&Bs[kk][tx * 8];
            float4 b1 = *(const float4*)&Bs[kk][tx * 8 + 4];
            float av[8] = {a0.x, a0.y, a0.z, a0.w, a1.x, a1.y, a1.z, a1.w};
            float bv[8] = {b0.x, b0.y, b0.z, b0.w, b1.x, b1.y, b1.z, b1.w};
#pragma unroll
            for (int m = 0; m < 8; m++)
#pragma unroll
                for (int n = 0; n < 8; n++)
                    acc[m][n] = fmaf(av[m], bv[n], acc[m][n]);
        }
        __syncthreads();
    }

    // epilogue: exponentiate in registers, accumulate statistics
    float inm[8], inj[8];
#pragma unroll
    for (int m = 0; m < 8; m++) inm[m] = g_inv_mp[ib + ty * 8 + m] * (1.0f / TAU);
#pragma unroll
    for (int n = 0; n < 8; n++) inj[n] = g_inv_sc[jb + tx * 8 + n];

    float rs[8] = {}, cs[8] = {}, pm[8] = {}, ps[8] = {};
#pragma unroll
    for (int m = 0; m < 8; m++)
#pragma unroll
        for (int n = 0; n < 8; n++) {
            float e = expf(acc[m][n] * inm[m] * inj[n]);
            acc[m][n] = e;
            rs[m] += e;
            cs[n] += e;
        }

    // Pmp: pos[i][j] (coalesced int4 row reads)
#pragma unroll
    for (int m = 0; m < 8; m++) {
        size_t base = (size_t)(ib + ty * 8 + m) * NN + jb + tx * 8;
        int4 p0 = *(const int4*)(pos + base);
        int4 p1 = *(const int4*)(pos + base + 4);
        float pv[8] = {(float)p0.x, (float)p0.y, (float)p0.z, (float)p0.w,
                       (float)p1.x, (float)p1.y, (float)p1.z, (float)p1.w};
#pragma unroll
        for (int n = 0; n < 8; n++) pm[m] = fmaf(acc[m][n], pv[n], pm[m]);
    }

    // Psc: pos[j][i] (int4 reads along i; L1 reuses lines within the tile)
#pragma unroll
    for (int n = 0; n < 8; n++) {
        size_t base = (size_t)(jb + tx * 8 + n) * NN + ib + ty * 8;
        int4 p0 = *(const int4*)(pos + base);
        int4 p1 = *(const int4*)(pos + base + 4);
        float pv[8] = {(float)p0.x, (float)p0.y, (float)p0.z, (float)p0.w,
                       (float)p1.x, (float)p1.y, (float)p1.z, (float)p1.w};
#pragma unroll
        for (int m = 0; m < 8; m++) ps[n] = fmaf(acc[m][n], pv[m], ps[n]);
    }

    // block reductions (one global atomic per row/col element per block)
    // rowsum
    __syncthreads();
#pragma unroll
    for (int m = 0; m < 8; m++) red[tid * 8 + m] = rs[m];
    __syncthreads();
    if (tid < 128) {
        int r = tid, tyb = r >> 3, mm = r & 7;
        float s = 0.f;
#pragma unroll
        for (int t2 = 0; t2 < 16; t2++) s += red[(tyb * 16 + t2) * 8 + mm];
        atomicAdd(&g_rowsum[ib + r], s);
    }
    __syncthreads();
    // Pmp
#pragma unroll
    for (int m = 0; m < 8; m++) red[tid * 8 + m] = pm[m];
    __syncthreads();
    if (tid < 128) {
        int r = tid, tyb = r >> 3, mm = r & 7;
        float s = 0.f;
#pragma unroll
        for (int t2 = 0; t2 < 16; t2++) s += red[(tyb * 16 + t2) * 8 + mm];
        atomicAdd(&g_pmp[ib + r], s);
    }
    __syncthreads();
    // colsum
#pragma unroll
    for (int n = 0; n < 8; n++) red[tid * 8 + n] = cs[n];
    __syncthreads();
    if (tid < 128) {
        int c = tid, txb = c >> 3, nn2 = c & 7;
        float s = 0.f;
#pragma unroll
        for (int t2 = 0; t2 < 16; t2++) s += red[(t2 * 16 + txb) * 8 + nn2];
        atomicAdd(&g_colsum[jb + c], s);
    }
    __syncthreads();
    // Psc
#pragma unroll
    for (int n = 0; n < 8; n++) red[tid * 8 + n] = ps[n];
    __syncthreads();
    if (tid < 128) {
        int c = tid, txb = c >> 3, nn2 = c & 7;
        float s = 0.f;
#pragma unroll
        for (int t2 = 0; t2 < 16; t2++) s += red[(t2 * 16 + txb) * 8 + nn2];
        atomicAdd(&g_psc[jb + c], s);
    }
}

// ---------------- final scalar reduction ----------------
__global__ void final_kernel(float* __restrict__ out) {
    int t = threadIdx.x;  // 256
    float s = 0.f;
    for (int i = t; i < NN; i += 256) {
        float lmp = logf(g_pmp[i]) - logf(g_rowsum[i] + EPSV);
        float lsc = logf(g_psc[i]) - logf(g_colsum[i] + EPSV);
        s += LAM * lmp + (1.0f - LAM) * lsc;
    }
#pragma unroll
    for (int o = 16; o > 0; o >>= 1) s += __shfl_down_sync(0xffffffffu, s, o);
    __shared__ float sr[8];
    if ((t & 31) == 0) sr[t >> 5] = s;
    __syncthreads();
    if (t == 0) {
        float tot = 0.f;
#pragma unroll
        for (int w = 0; w < 8; w++) tot += sr[w];
        out[0] = -tot / (float)NN;
    }
}

// ---------------- launch ----------------
extern "C" void kernel_launch(void* const* d_in, const int* in_sizes, int n_in,
                              void* d_out, int out_size) {
    const float* z_mp = (const float*)d_in[0];
    const float* z_sc = (const float*)d_in[1];
    const int* pos = (const int*)d_in[2];
    const float* W1 = (const float*)d_in[3];
    const float* b1 = (const float*)d_in[4];
    const float* W2 = (const float*)d_in[5];
    const float* b2 = (const float*)d_in[6];

    float *p_h, *p_zp_mp, *p_zp_sc, *p_inv_mp, *p_inv_sc;
    cudaGetSymbolAddress((void**)&p_h, g_h);
    cudaGetSymbolAddress((void**)&p_zp_mp, g_zp_mp);
    cudaGetSymbolAddress((void**)&p_zp_sc, g_zp_sc);
    cudaGetSymbolAddress((void**)&p_inv_mp, g_inv_mp);
    cudaGetSymbolAddress((void**)&p_inv_sc, g_inv_sc);

    zero_kernel<<<NN / 256, 256>>>();

    dim3 mlp_grid(HH / 128, NN / 128);
    mlp_gemm_kernel<true><<<mlp_grid, 256>>>(z_mp, W1, b1, p_h);
    mlp_gemm_kernel<false><<<mlp_grid, 256>>>(p_h, W2, b2, p_zp_mp);
    mlp_gemm_kernel<true><<<mlp_grid, 256>>>(z_sc, W1, b1, p_h);
    mlp_gemm_kernel<false><<<mlp_grid, 256>>>(p_h, W2, b2, p_zp_sc);

    norm_kernel<<<NN, 128>>>(p_zp_mp, p_inv_mp);
    norm_kernel<<<NN, 128>>>(p_zp_sc, p_inv_sc);

    pair_kernel<<<dim3(NN / 128, NN / 128), 256>>>(pos);

    final_kernel<<<1, 256>>>((float*)d_out);
}

// round 4
// speedup vs baseline: 2.1982x; 2.1932x over previous
#include <cuda_runtime.h>
#include <cuda_bf16.h>
#include <math.h>
#include <stdint.h>

#define NN 8192
#define HH 512
#define TAU 0.8f
#define LAM 0.5f
#define EPSV 1e-8f

#define KC 32
#define NCH (HH / KC)            // 16 chunks
#define SROWB 80                 // 32 bf16 + 8 pad = 40 bf16 = 80 bytes per row
#define ABYTES (128 * SROWB)     // 10240 per operand array
#define STAGEB (4 * ABYTES)      // 40960 per stage
#define SMEM_DYN (2 * STAGEB)    // 81920

__device__ __nv_bfloat16 g_ah[NN * HH], g_al[NN * HH];
__device__ __nv_bfloat16 g_hh[NN * HH], g_hl[NN * HH];
__device__ __nv_bfloat16 g_mph[NN * HH], g_mpl[NN * HH];
__device__ __nv_bfloat16 g_sch[NN * HH], g_scl[NN * HH];
__device__ __nv_bfloat16 g_w1h[HH * HH], g_w1l[HH * HH];
__device__ __nv_bfloat16 g_w2h[HH * HH], g_w2l[HH * HH];
__device__ uint32_t g_posb[(size_t)NN * (NN / 32)];
__device__ float g_inv_mp[NN], g_inv_sc[NN];
__device__ float g_rowsum[NN], g_colsum[NN], g_pmp[NN], g_psc[NN];

__device__ __forceinline__ uint32_t smem_u32(const void* p) {
    uint32_t a;
    asm("{ .reg .u64 t; cvta.to.shared.u64 t, %1; cvt.u32.u64 %0, t; }" : "=r"(a) : "l"(p));
    return a;
}
__device__ __forceinline__ void cp16(uint32_t s, const void* g) {
    asm volatile("cp.async.cg.shared.global [%0], [%1], 16;" :: "r"(s), "l"(g));
}
#define CP_COMMIT() asm volatile("cp.async.commit_group;" ::: "memory")
#define CP_WAIT1() asm volatile("cp.async.wait_group 1;" ::: "memory")
#define CP_WAIT0() asm volatile("cp.async.wait_group 0;" ::: "memory")

#define LDSM4(R, ADDR) \
    asm volatile("ldmatrix.sync.aligned.m8n8.x4.shared.b16 {%0,%1,%2,%3}, [%4];" \
        : "=r"((R)[0]), "=r"((R)[1]), "=r"((R)[2]), "=r"((R)[3]) : "r"(ADDR))

#define MMA(C, A, B0, B1) \
    asm volatile("mma.sync.aligned.m16n8k16.row.col.f32.bf16.bf16.f32 " \
        "{%0,%1,%2,%3},{%4,%5,%6,%7},{%8,%9},{%0,%1,%2,%3};" \
        : "+f"((C)[0]), "+f"((C)[1]), "+f"((C)[2]), "+f"((C)[3]) \
        : "r"((A)[0]), "r"((A)[1]), "r"((A)[2]), "r"((A)[3]), "r"(B0), "r"(B1))

__device__ __forceinline__ uint32_t pk2(float a, float b) {
    __nv_bfloat162 t = __floats2bfloat162_rn(a, b);
    return *reinterpret_cast<uint32_t*>(&t);
}

// ---- shared mainloop: 128x128 tile, K=512, 3-term split-bf16, HMMA ----
__device__ __forceinline__ void gemm_mainloop(
    uint32_t dsm32,
    const __nv_bfloat16* __restrict__ Ah, const __nv_bfloat16* __restrict__ Al,
    const __nv_bfloat16* __restrict__ Bh, const __nv_bfloat16* __restrict__ Bl,
    float cacc[2][8][4]) {
    const int tid = threadIdx.x;
    const int wid = tid >> 5, lane = tid & 31;
    const int wm = wid >> 1, wn = wid & 1;

    const __nv_bfloat16* srcs[4] = {Ah, Al, Bh, Bl};

    // prologue: chunk 0 -> stage 0
    {
        const int k0 = 0;
#pragma unroll
        for (int a = 0; a < 4; ++a) {
            uint32_t sb = dsm32 + a * ABYTES;
#pragma unroll
            for (int it = 0; it < 2; ++it) {
                int id = it * 256 + tid;
                int row = id >> 2, cc = id & 3;
                cp16(sb + row * SROWB + cc * 16, srcs[a] + (size_t)row * HH + k0 + cc * 8);
            }
        }
        CP_COMMIT();
    }

    const int lrow = lane & 15, lhalf = lane >> 4;

    for (int c = 0; c < NCH; ++c) {
        if (c + 1 < NCH) {
            const int k0 = (c + 1) * KC;
            const uint32_t st = ((c + 1) & 1) * STAGEB;
#pragma unroll
            for (int a = 0; a < 4; ++a) {
                uint32_t sb = dsm32 + st + a * ABYTES;
#pragma unroll
                for (int it = 0; it < 2; ++it) {
                    int id = it * 256 + tid;
                    int row = id >> 2, cc = id & 3;
                    cp16(sb + row * SROWB + cc * 16, srcs[a] + (size_t)row * HH + k0 + cc * 8);
                }
            }
            CP_COMMIT();
            CP_WAIT1();
        } else {
            CP_WAIT0();
        }
        __syncthreads();

        const uint32_t st = (c & 1) * STAGEB;
        const uint32_t abh = dsm32 + st;                  // Ah
        const uint32_t abl = dsm32 + st + ABYTES;         // Al
        const uint32_t bbh = dsm32 + st + 2 * ABYTES;     // Bh
        const uint32_t bbl = dsm32 + st + 3 * ABYTES;     // Bl

#pragma unroll
        for (int kk = 0; kk < 2; ++kk) {
            uint32_t ah[2][4], al[2][4];
#pragma unroll
            for (int mf = 0; mf < 2; ++mf) {
                uint32_t off = (uint32_t)((wm * 32 + mf * 16 + lrow) * SROWB + kk * 32 + lhalf * 16);
                LDSM4(ah[mf], abh + off);
                LDSM4(al[mf], abl + off);
            }
            uint32_t bh[4][4], bl[4][4];
#pragma unroll
            for (int nb = 0; nb < 4; ++nb) {
                uint32_t off = (uint32_t)((wn * 64 + nb * 16 + lrow) * SROWB + kk * 32 + lhalf * 16);
                LDSM4(bh[nb], bbh + off);
                LDSM4(bl[nb], bbl + off);
            }
#pragma unroll
            for (int mf = 0; mf < 2; ++mf)
#pragma unroll
                for (int nb = 0; nb < 4; ++nb) {
                    MMA(cacc[mf][nb * 2 + 0], ah[mf], bh[nb][0], bh[nb][2]);
                    MMA(cacc[mf][nb * 2 + 1], ah[mf], bh[nb][1], bh[nb][3]);
                    MMA(cacc[mf][nb * 2 + 0], ah[mf], bl[nb][0], bl[nb][2]);
                    MMA(cacc[mf][nb * 2 + 1], ah[mf], bl[nb][1], bl[nb][3]);
                    MMA(cacc[mf][nb * 2 + 0], al[mf], bh[nb][0], bh[nb][2]);
                    MMA(cacc[mf][nb * 2 + 1], al[mf], bh[nb][1], bh[nb][3]);
                }
        }
        __syncthreads();
    }
}

// ---- MLP: C = act(A @ W^T + b), split-bf16 out ----
template <bool ELU_>
__global__ void __launch_bounds__(256, 1) mlp_kernel(
    const __nv_bfloat16* __restrict__ Ah, const __nv_bfloat16* __restrict__ Al,
    const float* __restrict__ bias,
    __nv_bfloat16* __restrict__ Ch, __nv_bfloat16* __restrict__ Cl,
    const __nv_bfloat16* __restrict__ Wh, const __nv_bfloat16* __restrict__ Wl) {
    extern __shared__ __align__(16) char dsm[];
    __shared__ float sbias[128];
    const uint32_t dsm32 = smem_u32(dsm);
    const int tid = threadIdx.x;
    const int wid = tid >> 5, lane = tid & 31;
    const int wm = wid >> 1, wn = wid & 1;
    const int ib = blockIdx.y * 128, jb = blockIdx.x * 128;

    if (tid < 128) sbias[tid] = bias[jb + tid];

    float cacc[2][8][4] = {};
    gemm_mainloop(dsm32, Ah + (size_t)ib * HH, Al + (size_t)ib * HH,
                  Wh + (size_t)jb * HH, Wl + (size_t)jb * HH, cacc);
    __syncthreads();

#pragma unroll
    for (int mf = 0; mf < 2; ++mf)
#pragma unroll
        for (int nf = 0; nf < 8; ++nf)
#pragma unroll
            for (int h = 0; h < 2; ++h) {
                int i_l = wm * 32 + mf * 16 + (lane >> 2) + h * 8;
                int j_l = wn * 64 + nf * 8 + (lane & 3) * 2;
                float x0 = cacc[mf][nf][h * 2 + 0] + sbias[j_l];
                float x1 = cacc[mf][nf][h * 2 + 1] + sbias[j_l + 1];
                if (ELU_) {
                    x0 = (x0 > 0.f) ? x0 : expm1f(x0);
                    x1 = (x1 > 0.f) ? x1 : expm1f(x1);
                }
                float h0 = __bfloat162float(__float2bfloat16(x0));
                float h1 = __bfloat162float(__float2bfloat16(x1));
                size_t off = (size_t)(ib + i_l) * HH + jb + j_l;
                *(uint32_t*)(Ch + off) = pk2(h0, h1);
                *(uint32_t*)(Cl + off) = pk2(x0 - h0, x1 - h1);
            }
}

// ---- fused pairwise kernel ----
#define ETS 133
__global__ void __launch_bounds__(256, 1) pair_kernel() {
    extern __shared__ __align__(16) char dsm[];
    __shared__ float sjv[128];
    const uint32_t dsm32 = smem_u32(dsm);
    const int tid = threadIdx.x;
    const int wid = tid >> 5, lane = tid & 31;
    const int wm = wid >> 1, wn = wid & 1;
    const int ib = blockIdx.y * 128, jb = blockIdx.x * 128;

    if (tid < 128) sjv[tid] = g_inv_sc[jb + tid];

    float cacc[2][8][4] = {};
    gemm_mainloop(dsm32, g_mph + (size_t)ib * HH, g_mpl + (size_t)ib * HH,
                  g_sch + (size_t)jb * HH, g_scl + (size_t)jb * HH, cacc);
    __syncthreads();

    // exp in registers -> smem tile
    float* ET = (float*)dsm;
    float invi[2][2];
#pragma unroll
    for (int mf = 0; mf < 2; ++mf)
#pragma unroll
        for (int h = 0; h < 2; ++h)
            invi[mf][h] = g_inv_mp[ib + wm * 32 + mf * 16 + (lane >> 2) + h * 8] * (1.0f / TAU);

#pragma unroll
    for (int mf = 0; mf < 2; ++mf)
#pragma unroll
        for (int nf = 0; nf < 8; ++nf)
#pragma unroll
            for (int cr = 0; cr < 4; ++cr) {
                int i_l = wm * 32 + mf * 16 + (lane >> 2) + (cr >> 1) * 8;
                int j_l = wn * 64 + nf * 8 + (lane & 3) * 2 + (cr & 1);
                float e = __expf(cacc[mf][nf][cr] * invi[mf][cr >> 1] * sjv[j_l]);
                ET[i_l * ETS + j_l] = e;
            }
    __syncthreads();

    if (tid < 128) {
        // rows: rowsum + pmp
        const int r = tid;
        const float* row = ET + r * ETS;
        float rs = 0.f, pm = 0.f;
        const size_t pb = (size_t)(ib + r) * (NN / 32) + (jb >> 5);
#pragma unroll
        for (int w = 0; w < 4; ++w) {
            uint32_t u = g_posb[pb + w];
#pragma unroll
            for (int b = 0; b < 32; ++b) {
                float e = row[w * 32 + b];
                rs += e;
                if ((u >> b) & 1u) pm += e;
            }
        }
        atomicAdd(&g_rowsum[ib + r], rs);
        atomicAdd(&g_pmp[ib + r], pm);
    } else {
        // cols: colsum + psc
        const int cidx = tid - 128;
        float cs = 0.f, ps = 0.f;
        const size_t pb = (size_t)(jb + cidx) * (NN / 32) + (ib >> 5);
#pragma unroll
        for (int w = 0; w < 4; ++w) {
            uint32_t u = g_posb[pb + w];
#pragma unroll
            for (int b = 0; b < 32; ++b) {
                float e = ET[(w * 32 + b) * ETS + cidx];
                cs += e;
                if ((u >> b) & 1u) ps += e;
            }
        }
        atomicAdd(&g_colsum[jb + cidx], cs);
        atomicAdd(&g_psc[jb + cidx], ps);
    }
}

// ---- small kernels ----
__global__ void zero_kernel() {
    int i = blockIdx.x * blockDim.x + threadIdx.x;
    if (i < NN) { g_rowsum[i] = 0.f; g_colsum[i] = 0.f; g_pmp[i] = 0.f; g_psc[i] = 0.f; }
}

__global__ void split_kernel(const float* __restrict__ x,
                             __nv_bfloat16* __restrict__ hi, __nv_bfloat16* __restrict__ lo, int n8) {
    int t = blockIdx.x * blockDim.x + threadIdx.x;
    if (t >= n8) return;
    size_t b = (size_t)t * 8;
    float4 v0 = *(const float4*)(x + b);
    float4 v1 = *(const float4*)(x + b + 4);
    float xs[8] = {v0.x, v0.y, v0.z, v0.w, v1.x, v1.y, v1.z, v1.w};
    float hs[8], ls[8];
#pragma unroll
    for (int k = 0; k < 8; ++k) {
        float h = __bfloat162float(__float2bfloat16(xs[k]));
        hs[k] = h; ls[k] = xs[k] - h;
    }
    uint4 vh, vl;
    vh.x = pk2(hs[0], hs[1]); vh.y = pk2(hs[2], hs[3]); vh.z = pk2(hs[4], hs[5]); vh.w = pk2(hs[6], hs[7]);
    vl.x = pk2(ls[0], ls[1]); vl.y = pk2(ls[2], ls[3]); vl.z = pk2(ls[4], ls[5]); vl.w = pk2(ls[6], ls[7]);
    *(uint4*)(hi + b) = vh;
    *(uint4*)(lo + b) = vl;
}

__global__ void norm_kernel(const __nv_bfloat16* __restrict__ hi, const __nv_bfloat16* __restrict__ lo,
                            float* __restrict__ inv) {
    int row = blockIdx.x, t = threadIdx.x;
    size_t base = (size_t)row * HH + t * 4;
    float s = 0.f;
#pragma unroll
    for (int k = 0; k < 4; ++k) {
        float v = __bfloat162float(hi[base + k]) + __bfloat162float(lo[base + k]);
        s += v * v;
    }
#pragma unroll
    for (int o = 16; o > 0; o >>= 1) s += __shfl_down_sync(0xffffffffu, s, o);
    __shared__ float sr[4];
    if ((t & 31) == 0) sr[t >> 5] = s;
    __syncthreads();
    if (t == 0) inv[row] = rsqrtf(sr[0] + sr[1] + sr[2] + sr[3]);
}

__global__ void posbits_kernel(const int* __restrict__ pos) {
    int row = blockIdx.x;
    int w0 = threadIdx.x >> 5, lid = threadIdx.x & 31;
    for (int w = w0; w < NN / 32; w += 8) {
        int v = pos[(size_t)row * NN + w * 32 + lid];
        unsigned m = __ballot_sync(0xffffffffu, v != 0);
        if (lid == 0) g_posb[(size_t)row * (NN / 32) + w] = m;
    }
}

__global__ void final_kernel(float* __restrict__ out) {
    int t = threadIdx.x;
    float s = 0.f;
    for (int i = t; i < NN; i += 256) {
        float lmp = logf(g_pmp[i]) - logf(g_rowsum[i] + EPSV);
        float lsc = logf(g_psc[i]) - logf(g_colsum[i] + EPSV);
        s += LAM * lmp + (1.0f - LAM) * lsc;
    }
#pragma unroll
    for (int o = 16; o > 0; o >>= 1) s += __shfl_down_sync(0xffffffffu, s, o);
    __shared__ float sr[8];
    if ((t & 31) == 0) sr[t >> 5] = s;
    __syncthreads();
    if (t == 0) {
        float tot = 0.f;
#pragma unroll
        for (int w = 0; w < 8; w++) tot += sr[w];
        out[0] = -tot / (float)NN;
    }
}

extern "C" void kernel_launch(void* const* d_in, const int* in_sizes, int n_in,
                              void* d_out, int out_size) {
    const float* z_mp = (const float*)d_in[0];
    const float* z_sc = (const float*)d_in[1];
    const int* pos = (const int*)d_in[2];
    const float* W1 = (const float*)d_in[3];
    const float* b1 = (const float*)d_in[4];
    const float* W2 = (const float*)d_in[5];
    const float* b2 = (const float*)d_in[6];

    __nv_bfloat16 *ah, *al, *hh, *hl, *mph, *mpl, *sch, *scl, *w1h, *w1l, *w2h, *w2l;
    float *inv_mp, *inv_sc;
    cudaGetSymbolAddress((void**)&ah, g_ah);   cudaGetSymbolAddress((void**)&al, g_al);
    cudaGetSymbolAddress((void**)&hh, g_hh);   cudaGetSymbolAddress((void**)&hl, g_hl);
    cudaGetSymbolAddress((void**)&mph, g_mph); cudaGetSymbolAddress((void**)&mpl, g_mpl);
    cudaGetSymbolAddress((void**)&sch, g_sch); cudaGetSymbolAddress((void**)&scl, g_scl);
    cudaGetSymbolAddress((void**)&w1h, g_w1h); cudaGetSymbolAddress((void**)&w1l, g_w1l);
    cudaGetSymbolAddress((void**)&w2h, g_w2h); cudaGetSymbolAddress((void**)&w2l, g_w2l);
    cudaGetSymbolAddress((void**)&inv_mp, g_inv_mp);
    cudaGetSymbolAddress((void**)&inv_sc, g_inv_sc);

    static bool attr_done = false;
    if (!attr_done) {
        cudaFuncSetAttribute(mlp_kernel<true>, cudaFuncAttributeMaxDynamicSharedMemorySize, SMEM_DYN);
        cudaFuncSetAttribute(mlp_kernel<false>, cudaFuncAttributeMaxDynamicSharedMemorySize, SMEM_DYN);
        cudaFuncSetAttribute(pair_kernel, cudaFuncAttributeMaxDynamicSharedMemorySize, SMEM_DYN);
        attr_done = true;
    }

    zero_kernel<<<NN / 256, 256>>>();
    posbits_kernel<<<NN, 256>>>(pos);

    split_kernel<<<(NN * HH / 8 + 255) / 256, 256>>>(z_mp, ah, al, NN * HH / 8);
    split_kernel<<<(HH * HH / 8 + 255) / 256, 256>>>(W1, w1h, w1l, HH * HH / 8);
    split_kernel<<<(HH * HH / 8 + 255) / 256, 256>>>(W2, w2h, w2l, HH * HH / 8);

    dim3 mg(HH / 128, NN / 128);
    mlp_kernel<true><<<mg, 256, SMEM_DYN>>>(ah, al, b1, hh, hl, w1h, w1l);
    mlp_kernel<false><<<mg, 256, SMEM_DYN>>>(hh, hl, b2, mph, mpl, w2h, w2l);
    split_kernel<<<(NN * HH / 8 + 255) / 256, 256>>>(z_sc, ah, al, NN * HH / 8);
    mlp_kernel<true><<<mg, 256, SMEM_DYN>>>(ah, al, b1, hh, hl, w1h, w1l);
    mlp_kernel<false><<<mg, 256, SMEM_DYN>>>(hh, hl, b2, sch, scl, w2h, w2l);

    norm_kernel<<<NN, 128>>>(mph, mpl, inv_mp);
    norm_kernel<<<NN, 128>>>(sch, scl, inv_sc);

    pair_kernel<<<dim3(NN / 128, NN / 128), 256, SMEM_DYN>>>();

    final_kernel<<<1, 256>>>((float*)d_out);
}

// round 5
// speedup vs baseline: 4.8755x; 2.2179x over previous
#include <cuda_runtime.h>
#include <cuda_bf16.h>
#include <math.h>
#include <stdint.h>

#define NN 8192
#define HH 512
#define TAU 0.8f
#define LAM 0.5f
#define EPSV 1e-8f

#define KC 32
#define NCH (HH / KC)            // 16 chunks
#define SROWB 80                 // 32 bf16 (64B) + 16B pad per row
#define ABYTES (128 * SROWB)     // 10240 per operand array
#define STAGEB (2 * ABYTES)      // 20480 per stage (A + B)
#define MAINB (2 * STAGEB)       // 40960 double-buffered
#define ETS 133
#define ETB (128 * ETS * 4)      // 68096 epilogue tile
#define SMEM_PAIR 69632
#define SMEM_MLP 40960

__device__ __nv_bfloat16 g_a[NN * HH];
__device__ __nv_bfloat16 g_h[NN * HH];
__device__ __nv_bfloat16 g_mp[NN * HH];
__device__ __nv_bfloat16 g_sc[NN * HH];
__device__ __nv_bfloat16 g_w1[HH * HH];
__device__ __nv_bfloat16 g_w2[HH * HH];
__device__ uint32_t g_posb[(size_t)NN * (NN / 32)];
__device__ float g_inv_mp[NN], g_inv_sc[NN];
__device__ float g_rowsum[NN], g_colsum[NN], g_pmp[NN], g_psc[NN];

__device__ __forceinline__ uint32_t smem_u32(const void* p) {
    uint32_t a;
    asm("{ .reg .u64 t; cvta.to.shared.u64 t, %1; cvt.u32.u64 %0, t; }" : "=r"(a) : "l"(p));
    return a;
}
__device__ __forceinline__ void cp16(uint32_t s, const void* g) {
    asm volatile("cp.async.cg.shared.global [%0], [%1], 16;" :: "r"(s), "l"(g));
}
#define CP_COMMIT() asm volatile("cp.async.commit_group;" ::: "memory")
#define CP_WAIT1() asm volatile("cp.async.wait_group 1;" ::: "memory")
#define CP_WAIT0() asm volatile("cp.async.wait_group 0;" ::: "memory")

#define LDSM4(R, ADDR) \
    asm volatile("ldmatrix.sync.aligned.m8n8.x4.shared.b16 {%0,%1,%2,%3}, [%4];" \
        : "=r"((R)[0]), "=r"((R)[1]), "=r"((R)[2]), "=r"((R)[3]) : "r"(ADDR))

#define MMA(C, A, B0, B1) \
    asm volatile("mma.sync.aligned.m16n8k16.row.col.f32.bf16.bf16.f32 " \
        "{%0,%1,%2,%3},{%4,%5,%6,%7},{%8,%9},{%0,%1,%2,%3};" \
        : "+f"((C)[0]), "+f"((C)[1]), "+f"((C)[2]), "+f"((C)[3]) \
        : "r"((A)[0]), "r"((A)[1]), "r"((A)[2]), "r"((A)[3]), "r"(B0), "r"(B1))

__device__ __forceinline__ uint32_t pk2(float a, float b) {
    __nv_bfloat162 t = __floats2bfloat162_rn(a, b);
    return *reinterpret_cast<uint32_t*>(&t);
}

// ---- shared mainloop: 128x128 tile, K=512, single-term bf16 HMMA ----
__device__ __forceinline__ void gemm_mainloop(
    uint32_t dsm32,
    const __nv_bfloat16* __restrict__ A,
    const __nv_bfloat16* __restrict__ B,
    float cacc[2][8][4]) {
    const int tid = threadIdx.x;
    const int wid = tid >> 5, lane = tid & 31;
    const int wm = wid >> 1, wn = wid & 1;

    const __nv_bfloat16* srcs[2] = {A, B};

    // prologue: chunk 0 -> stage 0
    {
#pragma unroll
        for (int a = 0; a < 2; ++a) {
            uint32_t sb = dsm32 + a * ABYTES;
#pragma unroll
            for (int it = 0; it < 2; ++it) {
                int id = it * 256 + tid;
                int row = id >> 2, cc = id & 3;
                cp16(sb + row * SROWB + cc * 16, srcs[a] + (size_t)row * HH + cc * 8);
            }
        }
        CP_COMMIT();
    }

    const int lrow = lane & 15, lhalf = lane >> 4;

    for (int c = 0; c < NCH; ++c) {
        if (c + 1 < NCH) {
            const int k0 = (c + 1) * KC;
            const uint32_t st = ((c + 1) & 1) * STAGEB;
#pragma unroll
            for (int a = 0; a < 2; ++a) {
                uint32_t sb = dsm32 + st + a * ABYTES;
#pragma unroll
                for (int it = 0; it < 2; ++it) {
                    int id = it * 256 + tid;
                    int row = id >> 2, cc = id & 3;
                    cp16(sb + row * SROWB + cc * 16, srcs[a] + (size_t)row * HH + k0 + cc * 8);
                }
            }
            CP_COMMIT();
            CP_WAIT1();
        } else {
            CP_WAIT0();
        }
        __syncthreads();

        const uint32_t st = (c & 1) * STAGEB;
        const uint32_t ab = dsm32 + st;
        const uint32_t bb = dsm32 + st + ABYTES;

#pragma unroll
        for (int kk = 0; kk < 2; ++kk) {
            uint32_t ah[2][4];
#pragma unroll
            for (int mf = 0; mf < 2; ++mf) {
                uint32_t off = (uint32_t)((wm * 32 + mf * 16 + lrow) * SROWB + kk * 32 + lhalf * 16);
                LDSM4(ah[mf], ab + off);
            }
            uint32_t bh[4][4];
#pragma unroll
            for (int nb = 0; nb < 4; ++nb) {
                uint32_t off = (uint32_t)((wn * 64 + nb * 16 + lrow) * SROWB + kk * 32 + lhalf * 16);
                LDSM4(bh[nb], bb + off);
            }
#pragma unroll
            for (int mf = 0; mf < 2; ++mf)
#pragma unroll
                for (int nb = 0; nb < 4; ++nb) {
                    MMA(cacc[mf][nb * 2 + 0], ah[mf], bh[nb][0], bh[nb][2]);
                    MMA(cacc[mf][nb * 2 + 1], ah[mf], bh[nb][1], bh[nb][3]);
                }
        }
        __syncthreads();
    }
}

// ---- MLP: C = act(A @ W^T + b), bf16 out ----
template <bool ELU_>
__global__ void __launch_bounds__(256, 2) mlp_kernel(
    const __nv_bfloat16* __restrict__ A, const float* __restrict__ bias,
    __nv_bfloat16* __restrict__ C, const __nv_bfloat16* __restrict__ W) {
    extern __shared__ __align__(16) char dsm[];
    __shared__ float sbias[128];
    const uint32_t dsm32 = smem_u32(dsm);
    const int tid = threadIdx.x;
    const int wid = tid >> 5, lane = tid & 31;
    const int wm = wid >> 1, wn = wid & 1;
    const int ib = blockIdx.y * 128, jb = blockIdx.x * 128;

    if (tid < 128) sbias[tid] = bias[jb + tid];

    float cacc[2][8][4] = {};
    gemm_mainloop(dsm32, A + (size_t)ib * HH, W + (size_t)jb * HH, cacc);
    __syncthreads();

#pragma unroll
    for (int mf = 0; mf < 2; ++mf)
#pragma unroll
        for (int nf = 0; nf < 8; ++nf)
#pragma unroll
            for (int h = 0; h < 2; ++h) {
                int i_l = wm * 32 + mf * 16 + (lane >> 2) + h * 8;
                int j_l = wn * 64 + nf * 8 + (lane & 3) * 2;
                float x0 = cacc[mf][nf][h * 2 + 0] + sbias[j_l];
                float x1 = cacc[mf][nf][h * 2 + 1] + sbias[j_l + 1];
                if (ELU_) {
                    x0 = (x0 > 0.f) ? x0 : expm1f(x0);
                    x1 = (x1 > 0.f) ? x1 : expm1f(x1);
                }
                size_t off = (size_t)(ib + i_l) * HH + jb + j_l;
                *(uint32_t*)(C + off) = pk2(x0, x1);
            }
}

// ---- fused pairwise kernel ----
__global__ void __launch_bounds__(256, 2) pair_kernel() {
    extern __shared__ __align__(16) char dsm[];
    __shared__ float sjv[128];
    const uint32_t dsm32 = smem_u32(dsm);
    const int tid = threadIdx.x;
    const int wid = tid >> 5, lane = tid & 31;
    const int wm = wid >> 1, wn = wid & 1;
    const int ib = blockIdx.y * 128, jb = blockIdx.x * 128;

    if (tid < 128) sjv[tid] = g_inv_sc[jb + tid];

    float cacc[2][8][4] = {};
    gemm_mainloop(dsm32, g_mp + (size_t)ib * HH, g_sc + (size_t)jb * HH, cacc);
    __syncthreads();

    // exp in registers -> smem tile
    float* ET = (float*)dsm;
    float invi[2][2];
#pragma unroll
    for (int mf = 0; mf < 2; ++mf)
#pragma unroll
        for (int h = 0; h < 2; ++h)
            invi[mf][h] = g_inv_mp[ib + wm * 32 + mf * 16 + (lane >> 2) + h * 8] * (1.0f / TAU);

#pragma unroll
    for (int mf = 0; mf < 2; ++mf)
#pragma unroll
        for (int nf = 0; nf < 8; ++nf)
#pragma unroll
            for (int cr = 0; cr < 4; ++cr) {
                int i_l = wm * 32 + mf * 16 + (lane >> 2) + (cr >> 1) * 8;
                int j_l = wn * 64 + nf * 8 + (lane & 3) * 2 + (cr & 1);
                float e = __expf(cacc[mf][nf][cr] * invi[mf][cr >> 1] * sjv[j_l]);
                ET[i_l * ETS + j_l] = e;
            }
    __syncthreads();

    if (tid < 128) {
        const int r = tid;
        const float* row = ET + r * ETS;
        float rs = 0.f, pm = 0.f;
        const size_t pb = (size_t)(ib + r) * (NN / 32) + (jb >> 5);
#pragma unroll
        for (int w = 0; w < 4; ++w) {
            uint32_t u = g_posb[pb + w];
#pragma unroll
            for (int b = 0; b < 32; ++b) {
                float e = row[w * 32 + b];
                rs += e;
                if ((u >> b) & 1u) pm += e;
            }
        }
        atomicAdd(&g_rowsum[ib + r], rs);
        atomicAdd(&g_pmp[ib + r], pm);
    } else {
        const int cidx = tid - 128;
        float cs = 0.f, ps = 0.f;
        const size_t pb = (size_t)(jb + cidx) * (NN / 32) + (ib >> 5);
#pragma unroll
        for (int w = 0; w < 4; ++w) {
            uint32_t u = g_posb[pb + w];
#pragma unroll
            for (int b = 0; b < 32; ++b) {
                float e = ET[(w * 32 + b) * ETS + cidx];
                cs += e;
                if ((u >> b) & 1u) ps += e;
            }
        }
        atomicAdd(&g_colsum[jb + cidx], cs);
        atomicAdd(&g_psc[jb + cidx], ps);
    }
}

// ---- small kernels ----
__global__ void zero_kernel() {
    int i = blockIdx.x * blockDim.x + threadIdx.x;
    if (i < NN) { g_rowsum[i] = 0.f; g_colsum[i] = 0.f; g_pmp[i] = 0.f; g_psc[i] = 0.f; }
}

__global__ void tobf16_kernel(const float* __restrict__ x,
                              __nv_bfloat16* __restrict__ o, int n8) {
    int t = blockIdx.x * blockDim.x + threadIdx.x;
    if (t >= n8) return;
    size_t b = (size_t)t * 8;
    float4 v0 = *(const float4*)(x + b);
    float4 v1 = *(const float4*)(x + b + 4);
    uint4 vh;
    vh.x = pk2(v0.x, v0.y); vh.y = pk2(v0.z, v0.w);
    vh.z = pk2(v1.x, v1.y); vh.w = pk2(v1.z, v1.w);
    *(uint4*)(o + b) = vh;
}

__global__ void norm_kernel(const __nv_bfloat16* __restrict__ z, float* __restrict__ inv) {
    int row = blockIdx.x, t = threadIdx.x;  // 128 threads
    size_t base = (size_t)row * HH + t * 4;
    float s = 0.f;
#pragma unroll
    for (int k = 0; k < 4; ++k) {
        float v = __bfloat162float(z[base + k]);
        s += v * v;
    }
#pragma unroll
    for (int o = 16; o > 0; o >>= 1) s += __shfl_down_sync(0xffffffffu, s, o);
    __shared__ float sr[4];
    if ((t & 31) == 0) sr[t >> 5] = s;
    __syncthreads();
    if (t == 0) inv[row] = rsqrtf(sr[0] + sr[1] + sr[2] + sr[3]);
}

__global__ void posbits_kernel(const int* __restrict__ pos) {
    int row = blockIdx.x;
    int w0 = threadIdx.x >> 5, lid = threadIdx.x & 31;
    for (int w = w0; w < NN / 32; w += 8) {
        int v = pos[(size_t)row * NN + w * 32 + lid];
        unsigned m = __ballot_sync(0xffffffffu, v != 0);
        if (lid == 0) g_posb[(size_t)row * (NN / 32) + w] = m;
    }
}

__global__ void final_kernel(float* __restrict__ out) {
    int t = threadIdx.x;
    float s = 0.f;
    for (int i = t; i < NN; i += 256) {
        float lmp = logf(g_pmp[i]) - logf(g_rowsum[i] + EPSV);
        float lsc = logf(g_psc[i]) - logf(g_colsum[i] + EPSV);
        s += LAM * lmp + (1.0f - LAM) * lsc;
    }
#pragma unroll
    for (int o = 16; o > 0; o >>= 1) s += __shfl_down_sync(0xffffffffu, s, o);
    __shared__ float sr[8];
    if ((t & 31) == 0) sr[t >> 5] = s;
    __syncthreads();
    if (t == 0) {
        float tot = 0.f;
#pragma unroll
        for (int w = 0; w < 8; w++) tot += sr[w];
        out[0] = -tot / (float)NN;
    }
}

extern "C" void kernel_launch(void* const* d_in, const int* in_sizes, int n_in,
                              void* d_out, int out_size) {
    const float* z_mp = (const float*)d_in[0];
    const float* z_sc = (const float*)d_in[1];
    const int* pos = (const int*)d_in[2];
    const float* W1 = (const float*)d_in[3];
    const float* b1 = (const float*)d_in[4];
    const float* W2 = (const float*)d_in[5];
    const float* b2 = (const float*)d_in[6];

    __nv_bfloat16 *a, *h, *mp, *sc, *w1, *w2;
    float *inv_mp, *inv_sc;
    cudaGetSymbolAddress((void**)&a, g_a);
    cudaGetSymbolAddress((void**)&h, g_h);
    cudaGetSymbolAddress((void**)&mp, g_mp);
    cudaGetSymbolAddress((void**)&sc, g_sc);
    cudaGetSymbolAddress((void**)&w1, g_w1);
    cudaGetSymbolAddress((void**)&w2, g_w2);
    cudaGetSymbolAddress((void**)&inv_mp, g_inv_mp);
    cudaGetSymbolAddress((void**)&inv_sc, g_inv_sc);

    static bool attr_done = false;
    if (!attr_done) {
        cudaFuncSetAttribute(mlp_kernel<true>, cudaFuncAttributeMaxDynamicSharedMemorySize, SMEM_MLP);
        cudaFuncSetAttribute(mlp_kernel<false>, cudaFuncAttributeMaxDynamicSharedMemorySize, SMEM_MLP);
        cudaFuncSetAttribute(pair_kernel, cudaFuncAttributeMaxDynamicSharedMemorySize, SMEM_PAIR);
        attr_done = true;
    }

    zero_kernel<<<NN / 256, 256>>>();
    posbits_kernel<<<NN, 256>>>(pos);

    tobf16_kernel<<<(NN * HH / 8 + 255) / 256, 256>>>(z_mp, a, NN * HH / 8);
    tobf16_kernel<<<(HH * HH / 8 + 255) / 256, 256>>>(W1, w1, HH * HH / 8);
    tobf16_kernel<<<(HH * HH / 8 + 255) / 256, 256>>>(W2, w2, HH * HH / 8);

    dim3 mg(HH / 128, NN / 128);
    mlp_kernel<true><<<mg, 256, SMEM_MLP>>>(a, b1, h, w1);
    mlp_kernel<false><<<mg, 256, SMEM_MLP>>>(h, b2, mp, w2);
    tobf16_kernel<<<(NN * HH / 8 + 255) / 256, 256>>>(z_sc, a, NN * HH / 8);
    mlp_kernel<true><<<mg, 256, SMEM_MLP>>>(a, b1, h, w1);
    mlp_kernel<false><<<mg, 256, SMEM_MLP>>>(h, b2, sc, w2);

    norm_kernel<<<NN, 128>>>(mp, inv_mp);
    norm_kernel<<<NN, 128>>>(sc, inv_sc);

    pair_kernel<<<dim3(NN / 128, NN / 128), 256, SMEM_PAIR>>>();

    final_kernel<<<1, 256>>>((float*)d_out);
}